// round 4
// baseline (speedup 1.0000x reference)
#include <cuda_runtime.h>
#include <cuda_fp16.h>
#include <cstdint>

// Problem constants: B=4, L=4, N=2048, H=64, V=4, label_plus1=5
#define B_    4
#define L_    4
#define N_    2048
#define H_    64

// k_main pipeline config (CTA tile 64m x 64e, k-tile 64)
#define STAGES      8
#define A_ROW_STR   272                 // 256B row + 16B pad (bank stagger)
#define B_ROW_STR   144                 // 128B row + 16B pad
#define A_ST        (64 * A_ROW_STR)    // 17408
#define B_ST        (64 * B_ROW_STR)    // 9216
#define STAGE_BYTES (A_ST + B_ST)       // 26624
#define SMEM_MAIN   (128 + STAGES * STAGE_BYTES)   // mbars at front

// k_pre smem (floats): xs[64][68] | ts[64][68] | Ms[5][64][64] | sp[192]
#define PRE_XS   0
#define PRE_TS   (64 * 68)
#define PRE_MS   (2 * 64 * 68)
#define PRE_SP   (2 * 64 * 68 + 5 * 64 * 64)
#define PRE_FLTS (PRE_SP + 192)
#define SMEM_PRE (PRE_FLTS * 4)

// Scratch (device globals; no allocation allowed)
__device__ __align__(128) float  d_g0[B_ * N_ * H_];       // identity-label term (h @ M0)/5
__device__ __align__(128) __half d_gt[B_ * 4 * H_ * N_];   // g_{l+1} transposed [b,l,e,m] fp16

// ---------------------------------------------------------------------------
// Helpers
// ---------------------------------------------------------------------------
__device__ __forceinline__ uint32_t smem_u32(const void* p) {
    uint32_t a;
    asm("{ .reg .u64 t; cvta.to.shared.u64 t, %1; cvt.u32.u64 %0, t; }" : "=r"(a) : "l"(p));
    return a;
}
__device__ __forceinline__ void lds_v2(float& x, float& y, uint32_t a) {
    asm volatile("ld.shared.v2.f32 {%0, %1}, [%2];" : "=f"(x), "=f"(y) : "r"(a));
}
__device__ __forceinline__ uint32_t lds_b32(uint32_t a) {
    uint32_t v;
    asm volatile("ld.shared.b32 %0, [%1];" : "=r"(v) : "r"(a));
    return v;
}
__device__ __forceinline__ uint32_t cvt_h2(float hi, float lo) {   // pack {lo, hi}
    uint32_t r;
    asm("cvt.rn.f16x2.f32 %0, %1, %2;" : "=r"(r) : "f"(hi), "f"(lo));
    return r;
}
__device__ __forceinline__ void mma16816(float* c, const uint32_t* a, uint32_t b0, uint32_t b1) {
    asm volatile(
        "mma.sync.aligned.m16n8k16.row.col.f32.f16.f16.f32 "
        "{%0,%1,%2,%3}, {%4,%5,%6,%7}, {%8,%9}, {%0,%1,%2,%3};"
        : "+f"(c[0]), "+f"(c[1]), "+f"(c[2]), "+f"(c[3])
        : "r"(a[0]), "r"(a[1]), "r"(a[2]), "r"(a[3]), "r"(b0), "r"(b1));
}
__device__ __forceinline__ void mbar_init(uint32_t bar, uint32_t cnt) {
    asm volatile("mbarrier.init.shared.b64 [%0], %1;" :: "r"(bar), "r"(cnt) : "memory");
}
__device__ __forceinline__ void mbar_wait(uint32_t bar, uint32_t ph) {
    asm volatile(
        "{\n\t.reg .pred P;\n"
        "WL%=:\n\t"
        "mbarrier.try_wait.parity.acquire.cta.shared::cta.b64 P, [%0], %1, 0x989680;\n\t"
        "@!P bra WL%=;\n\t}"
        :: "r"(bar), "r"(ph) : "memory");
}
// expect_tx (counts as an arrival) + bulk async copy completing on the mbar
__device__ __forceinline__ void bulk_cp(uint32_t dst, const void* src, uint32_t bytes,
                                        uint32_t mbar) {
    asm volatile("mbarrier.arrive.expect_tx.shared.b64 _, [%0], %1;"
                 :: "r"(mbar), "r"(bytes) : "memory");
    asm volatile(
        "cp.async.bulk.shared::cluster.global.mbarrier::complete_tx::bytes [%0], [%1], %2, [%3];"
        :: "r"(dst), "l"(src), "r"(bytes), "r"(mbar) : "memory");
}
__device__ __forceinline__ void fma_x2(unsigned long long& c, unsigned long long a,
                                       unsigned long long b) {
    asm("fma.rn.f32x2 %0, %1, %2, %0;" : "+l"(c) : "l"(a), "l"(b));
}

// ---------------------------------------------------------------------------
// k_pre: M = (a@W)/5 (per-block, smem), h = tanh(LN(fc(x,feat))),
//        g0 = h@M0 -> d_g0;  g_j = h@M_j -> d_gt transposed fp16 (j=1..4)
// 128 blocks x 256 threads; block handles 64 rows.
// ---------------------------------------------------------------------------
__global__ void __launch_bounds__(256, 1)
k_pre(const float* __restrict__ x, const float* __restrict__ feat,
      const float* __restrict__ fcw, const float* __restrict__ fcb,
      const float* __restrict__ lng, const float* __restrict__ lnb,
      const float* __restrict__ W, const float* __restrict__ a) {
    extern __shared__ float sm[];
    float* xs = sm + PRE_XS;     // [64][68]: inputs, later h
    float* ts = sm + PRE_TS;     // [64][68]: fcw, later transpose buffer
    float* Ms = sm + PRE_MS;     // [5][64][64]
    float* sp = sm + PRE_SP;     // fcb | lng | lnb

    int tid = threadIdx.x;
    int row0 = blockIdx.x * 64;
    int b = row0 >> 11, nn0 = row0 & 2047;

    for (int i = tid; i < 64 * 64; i += 256)
        xs[(i >> 6) * 68 + (i & 63)] = x[(size_t)row0 * 64 + i];
    if (tid < 64) {
        xs[tid * 68 + 64] = feat[(size_t)(row0 + tid) * 2];
        xs[tid * 68 + 65] = feat[(size_t)(row0 + tid) * 2 + 1];
        sp[tid] = fcb[tid]; sp[64 + tid] = lng[tid]; sp[128 + tid] = lnb[tid];
    }
    for (int i = tid; i < 64 * 66; i += 256)
        ts[(i / 66) * 68 + (i % 66)] = fcw[i];
    for (int idx = tid; idx < 5 * 64 * 64; idx += 256) {
        int e = idx & 63, d = (idx >> 6) & 63, l = idx >> 12;
        float s = 0.f;
#pragma unroll
        for (int v = 0; v < 4; v++) s += a[l * 4 + v] * W[(d * 4 + v) * 64 + e];
        Ms[idx] = s * 0.2f;
    }
    __syncthreads();

    // ---- h: thread -> row r, 16 cols c0..c0+15 ----
    int r = tid >> 2, c0 = (tid & 3) * 16;
    float hacc[16];
#pragma unroll
    for (int j = 0; j < 16; j++) hacc[j] = sp[c0 + j];
#pragma unroll 2
    for (int k = 0; k < 66; k++) {
        float xv = xs[r * 68 + k];
#pragma unroll
        for (int j = 0; j < 16; j++) hacc[j] += ts[(c0 + j) * 68 + k] * xv;
    }
    float s = 0.f, sq = 0.f;
#pragma unroll
    for (int j = 0; j < 16; j++) { s += hacc[j]; sq += hacc[j] * hacc[j]; }
    s  += __shfl_xor_sync(0xffffffff, s, 1);  s  += __shfl_xor_sync(0xffffffff, s, 2);
    sq += __shfl_xor_sync(0xffffffff, sq, 1); sq += __shfl_xor_sync(0xffffffff, sq, 2);
    float mu  = s * (1.f / 64.f);
    float var = sq * (1.f / 64.f) - mu * mu;
    float inv = rsqrtf(var + 1e-5f);
#pragma unroll
    for (int j = 0; j < 16; j++)
        hacc[j] = tanhf((hacc[j] - mu) * inv * sp[64 + c0 + j] + sp[128 + c0 + j]);
    __syncthreads();
#pragma unroll
    for (int j = 0; j < 16; j++) xs[r * 68 + c0 + j] = hacc[j];
    __syncthreads();

    // ---- g_j = h @ M_j (f32x2) ----
    for (int j = 0; j < 5; j++) {
        unsigned long long acc[8];
#pragma unroll
        for (int p = 0; p < 8; p++) acc[p] = 0ull;
#pragma unroll 4
        for (int d = 0; d < 64; d++) {
            float hv = xs[r * 68 + d];
            unsigned long long hd;
            asm("mov.b64 %0, {%1, %1};" : "=l"(hd) : "r"(__float_as_uint(hv)));
            const unsigned long long* mp =
                (const unsigned long long*)&Ms[(j * 64 + d) * 64 + c0];
#pragma unroll
            for (int p = 0; p < 8; p++) fma_x2(acc[p], hd, mp[p]);
        }
        if (j == 0) {
            unsigned long long* dst =
                (unsigned long long*)(d_g0 + ((size_t)(row0 + r)) * 64 + c0);
#pragma unroll
            for (int p = 0; p < 8; p++) dst[p] = acc[p];
        } else {
            __syncthreads();
#pragma unroll
            for (int p = 0; p < 8; p++) {
                ts[(c0 + 2 * p) * 68 + r]     = __uint_as_float((uint32_t)acc[p]);
                ts[(c0 + 2 * p + 1) * 68 + r] = __uint_as_float((uint32_t)(acc[p] >> 32));
            }
            __syncthreads();
            int e = tid >> 2, ms = (tid & 3) * 16;
            __half2 h2[8];
#pragma unroll
            for (int q = 0; q < 8; q++)
                h2[q] = __floats2half2_rn(ts[e * 68 + ms + 2 * q], ts[e * 68 + ms + 2 * q + 1]);
            __half* dst = d_gt + ((size_t)(b * 4 + j - 1) * 64 + e) * 2048 + nn0 + ms;
            uint4* d4 = (uint4*)dst;
            d4[0] = *(uint4*)&h2[0];
            d4[1] = *(uint4*)&h2[4];
        }
    }
}

// ---------------------------------------------------------------------------
// k_main: out[b, n0..n0+63, :] = x + g0 + sum_{l,m} adj[b,l,n,m] * g[b,l,m,:]
// cp.async.bulk producer (128 bulks/stage), fp16 mma.sync consumer.
// 128 CTAs (32 n-tiles x 4 b), 8 warps, warp grid 4m x 2n, warp tile 16x32.
// ---------------------------------------------------------------------------
__global__ void __launch_bounds__(256, 1)
k_main(const float* __restrict__ adj, const float* __restrict__ x,
       float* __restrict__ out) {
    extern __shared__ __align__(128) char smem[];
    uint32_t sb = smem_u32(smem);
    int tid = threadIdx.x, wid = tid >> 5, lane = tid & 31;
    int gid = lane >> 2, tig = lane & 3;
    int b = blockIdx.y;
    int n0 = blockIdx.x * 64;
    int warp_m = wid & 3, warp_n = wid >> 2;

    const float*  adjb = adj  + (size_t)b * L_ * N_ * N_;
    const __half* gtb  = d_gt + (size_t)b * 4 * 64 * 2048;

    uint32_t mbar0 = sb;                 // 8 mbars, 8B each
    uint32_t data0 = sb + 128;

    if (tid < STAGES) mbar_init(mbar0 + 8 * tid, 128);
    __syncthreads();

    // issue one stage's loads (tid<64: A row tid; tid in [64,128): B row tid-64)
    auto issue = [&](int t) {
        if (tid < 128 && t < 128) {
            int slot = t & (STAGES - 1);
            int l = t >> 5, m0 = (t & 31) << 6;
            uint32_t base = data0 + slot * STAGE_BYTES;
            uint32_t mb = mbar0 + 8 * slot;
            if (tid < 64) {
                bulk_cp(base + tid * A_ROW_STR,
                        adjb + ((size_t)l * N_ + n0 + tid) * N_ + m0, 256, mb);
            } else {
                int e = tid - 64;
                bulk_cp(base + A_ST + e * B_ROW_STR,
                        gtb + ((size_t)l * 64 + e) * 2048 + m0, 128, mb);
            }
        }
    };

#pragma unroll
    for (int s = 0; s < STAGES; s++) issue(s);

    // fragment addressing
    uint32_t ar0_rel = (uint32_t)(warp_m * 16 + gid) * A_ROW_STR + tig * 8;
    uint32_t bn_rel[4];
#pragma unroll
    for (int nt = 0; nt < 4; nt++)
        bn_rel[nt] = A_ST + (uint32_t)(warp_n * 32 + nt * 8 + gid) * B_ROW_STR + tig * 4;

    float acc[4][4];
#pragma unroll
    for (int nt = 0; nt < 4; nt++)
#pragma unroll
        for (int q = 0; q < 4; q++) acc[nt][q] = 0.f;

#pragma unroll 1
    for (int t = 0; t < 128; t++) {
        int slot = t & (STAGES - 1);
        mbar_wait(mbar0 + 8 * slot, (t >> 3) & 1);

        uint32_t base = data0 + slot * STAGE_BYTES;
        uint32_t ar0 = base + ar0_rel;
#pragma unroll
        for (int ks = 0; ks < 4; ks++) {
            uint32_t afr[4];
#pragma unroll
            for (int kk = 0; kk < 2; kk++) {
                float x0, x1, y0, y1;
                lds_v2(x0, x1, ar0 + ks * 64 + kk * 32);
                lds_v2(y0, y1, ar0 + ks * 64 + kk * 32 + 8 * A_ROW_STR);
                afr[kk * 2 + 0] = cvt_h2(x1, x0);
                afr[kk * 2 + 1] = cvt_h2(y1, y0);
            }
#pragma unroll
            for (int nt = 0; nt < 4; nt++) {
                uint32_t b0 = lds_b32(base + bn_rel[nt] + ks * 32);
                uint32_t b1 = lds_b32(base + bn_rel[nt] + ks * 32 + 16);
                mma16816(acc[nt], afr, b0, b1);
            }
        }
        __syncthreads();
        issue(t + STAGES);
    }

    // Epilogue: out = acc + x + g0
#pragma unroll
    for (int h = 0; h < 2; h++) {
        int node = n0 + warp_m * 16 + gid + 8 * h;
        size_t base = ((size_t)b * N_ + node) * 64;
#pragma unroll
        for (int nt = 0; nt < 4; nt++) {
            int col = warp_n * 32 + nt * 8 + 2 * tig;
            float2 xv = *(const float2*)(x + base + col);
            float2 gv = *(const float2*)(d_g0 + base + col);
            float2 o;
            o.x = acc[nt][h * 2 + 0] + xv.x + gv.x;
            o.y = acc[nt][h * 2 + 1] + xv.y + gv.y;
            *(float2*)(out + base + col) = o;
        }
    }
}

// ---------------------------------------------------------------------------
// Launch: x, feature, adj, fc_w, fc_b, ln_g, ln_b, W, a
// ---------------------------------------------------------------------------
extern "C" void kernel_launch(void* const* d_in, const int* in_sizes, int n_in,
                              void* d_out, int out_size) {
    const float* x    = (const float*)d_in[0];
    const float* feat = (const float*)d_in[1];
    const float* adj  = (const float*)d_in[2];
    const float* fcw  = (const float*)d_in[3];
    const float* fcb  = (const float*)d_in[4];
    const float* lng  = (const float*)d_in[5];
    const float* lnb  = (const float*)d_in[6];
    const float* W    = (const float*)d_in[7];
    const float* a    = (const float*)d_in[8];
    float* out = (float*)d_out;

    cudaFuncSetAttribute(k_pre,  cudaFuncAttributeMaxDynamicSharedMemorySize, SMEM_PRE);
    cudaFuncSetAttribute(k_main, cudaFuncAttributeMaxDynamicSharedMemorySize, SMEM_MAIN);

    k_pre<<<128, 256, SMEM_PRE>>>(x, feat, fcw, fcb, lng, lnb, W, a);
    k_main<<<dim3(32, 4), 256, SMEM_MAIN>>>(adj, x, out);
}

// round 5
// speedup vs baseline: 1.1841x; 1.1841x over previous
#include <cuda_runtime.h>
#include <cuda_fp16.h>
#include <cstdint>

// Problem constants: B=4, L=4, N=2048, H=64, V=4, label_plus1=5
#define B_    4
#define L_    4
#define N_    2048
#define H_    64

// k_main pipeline (CTA tile 32m x 64e, k-tile 64, 2 CTAs/SM)
#define STAGES      6
#define A_ROW       272                  // 256B + 16B pad
#define B_ROW       144                  // 128B + 16B pad
#define A_ST        (32 * A_ROW)         // 8704
#define B_ST        (64 * B_ROW)         // 9216
#define STAGE_BYTES (A_ST + B_ST)        // 17920
#define SMEM_MAIN   (STAGES * STAGE_BYTES)   // 107520

// Scratch (device globals; no allocation allowed)
__device__ __align__(128) float  d_h [B_ * N_ * H_];
__device__ __align__(128) float  d_g0[B_ * N_ * H_];
__device__ __align__(128) __half d_gt[B_ * 4 * H_ * N_];   // [b,l,e,m] fp16
__device__ __align__(128) float  d_M [5 * H_ * H_];

// ---------------------------------------------------------------------------
// Helpers
// ---------------------------------------------------------------------------
__device__ __forceinline__ uint32_t smem_u32(const void* p) {
    uint32_t a;
    asm("{ .reg .u64 t; cvta.to.shared.u64 t, %1; cvt.u32.u64 %0, t; }" : "=r"(a) : "l"(p));
    return a;
}
__device__ __forceinline__ void cpasync16(uint32_t saddr, const void* gaddr) {
    asm volatile("cp.async.cg.shared.global [%0], [%1], 16;" :: "r"(saddr), "l"(gaddr));
}
__device__ __forceinline__ void lds_v2(float& x, float& y, uint32_t a) {
    asm volatile("ld.shared.v2.f32 {%0, %1}, [%2];" : "=f"(x), "=f"(y) : "r"(a));
}
__device__ __forceinline__ uint32_t lds_b32(uint32_t a) {
    uint32_t v;
    asm volatile("ld.shared.b32 %0, [%1];" : "=r"(v) : "r"(a));
    return v;
}
__device__ __forceinline__ uint32_t cvt_h2(float hi, float lo) {   // pack {lo, hi}
    uint32_t r;
    asm("cvt.rn.f16x2.f32 %0, %1, %2;" : "=r"(r) : "f"(hi), "f"(lo));
    return r;
}
__device__ __forceinline__ void mma16816(float* c, const uint32_t* a, uint32_t b0, uint32_t b1) {
    asm volatile(
        "mma.sync.aligned.m16n8k16.row.col.f32.f16.f16.f32 "
        "{%0,%1,%2,%3}, {%4,%5,%6,%7}, {%8,%9}, {%0,%1,%2,%3};"
        : "+f"(c[0]), "+f"(c[1]), "+f"(c[2]), "+f"(c[3])
        : "r"(a[0]), "r"(a[1]), "r"(a[2]), "r"(a[3]), "r"(b0), "r"(b1));
}
__device__ __forceinline__ float fast_tanh(float x) {
    // tanh(x) = 1 - 2/(exp(2x)+1); exp2f -> MUFU.EX2, __fdividef -> fast div
    float t = exp2f(x * 2.8853900817779268f);
    return 1.0f - __fdividef(2.0f, t + 1.0f);
}

// ---------------------------------------------------------------------------
// k_M: M = (a @ W) / 5
// ---------------------------------------------------------------------------
__global__ void k_M(const float* __restrict__ W, const float* __restrict__ a) {
    int idx = blockIdx.x * 256 + threadIdx.x;
    if (idx >= 5 * 64 * 64) return;
    int e = idx & 63, d = (idx >> 6) & 63, l = idx >> 12;
    float s = 0.f;
#pragma unroll
    for (int v = 0; v < 4; v++) s += a[l * 4 + v] * W[(d * 4 + v) * 64 + e];
    d_M[idx] = s * 0.2f;
}

// ---------------------------------------------------------------------------
// k_h: h = fast_tanh(LayerNorm(concat(x,feat) @ fc_w^T + fc_b))
// ---------------------------------------------------------------------------
__global__ void k_h(const float* __restrict__ x, const float* __restrict__ feat,
                    const float* __restrict__ fcw, const float* __restrict__ fcb,
                    const float* __restrict__ lng, const float* __restrict__ lnb) {
    __shared__ float sw[64 * 66];
    __shared__ float sp[3][64];
    __shared__ float srow[8][68];
    int tid = threadIdx.x;
    for (int i = tid; i < 64 * 66; i += 256) sw[i] = fcw[i];
    if (tid < 64) { sp[0][tid] = fcb[tid]; sp[1][tid] = lng[tid]; sp[2][tid] = lnb[tid]; }
    int warp = tid >> 5, lane = tid & 31;
    int row = blockIdx.x * 8 + warp;
    srow[warp][lane]      = x[row * 64 + lane];
    srow[warp][lane + 32] = x[row * 64 + lane + 32];
    if (lane < 2) srow[warp][64 + lane] = feat[row * 2 + lane];
    __syncthreads();

    float h0 = sp[0][lane], h1 = sp[0][lane + 32];
#pragma unroll
    for (int k = 0; k < 66; k++) {
        float xk = srow[warp][k];
        h0 += sw[lane * 66 + k] * xk;
        h1 += sw[(lane + 32) * 66 + k] * xk;
    }
    float s = h0 + h1, sq = h0 * h0 + h1 * h1;
#pragma unroll
    for (int o = 16; o > 0; o >>= 1) {
        s  += __shfl_xor_sync(0xffffffff, s,  o);
        sq += __shfl_xor_sync(0xffffffff, sq, o);
    }
    float mu  = s * (1.f / 64.f);
    float var = sq * (1.f / 64.f) - mu * mu;
    float inv = rsqrtf(var + 1e-5f);
    h0 = fast_tanh((h0 - mu) * inv * sp[1][lane]      + sp[2][lane]);
    h1 = fast_tanh((h1 - mu) * inv * sp[1][lane + 32] + sp[2][lane + 32]);
    d_h[row * 64 + lane]      = h0;
    d_h[row * 64 + lane + 32] = h1;
}

// ---------------------------------------------------------------------------
// k_g: g_j = h @ M_j. Grid (128 row-tiles, 5 j).
// j=0 -> d_g0 fp32; j>=1 -> d_gt [b,j-1,e,m] fp16 transposed
// ---------------------------------------------------------------------------
__global__ void k_g() {
    __shared__ float Ms[64][65];
    __shared__ float hs[64][65];
    int tid = threadIdx.x;
    int j = blockIdx.y;
    int row0 = blockIdx.x * 64;
    int b = row0 >> 11, nn0 = row0 & 2047;
    for (int i = tid; i < 4096; i += 256) {
        hs[i >> 6][i & 63] = d_h[(size_t)row0 * 64 + i];
        Ms[i >> 6][i & 63] = d_M[j * 4096 + i];
    }
    __syncthreads();
    int r = tid >> 2, c0 = (tid & 3) * 16;
    float acc[16];
#pragma unroll
    for (int c = 0; c < 16; c++) acc[c] = 0.f;
#pragma unroll 8
    for (int d = 0; d < 64; d++) {
        float hv = hs[r][d];
#pragma unroll
        for (int c = 0; c < 16; c++) acc[c] += hv * Ms[d][c0 + c];
    }
    if (j == 0) {
        float* dst = d_g0 + ((size_t)row0 + r) * 64 + c0;
#pragma unroll
        for (int c = 0; c < 16; c++) dst[c] = acc[c];
    } else {
        __syncthreads();
#pragma unroll
        for (int c = 0; c < 16; c++) Ms[c0 + c][r] = acc[c];   // transpose
        __syncthreads();
        int e = tid >> 2, ms = (tid & 3) * 16;
        __half2 h2[8];
#pragma unroll
        for (int q = 0; q < 8; q++)
            h2[q] = __floats2half2_rn(Ms[e][ms + 2 * q], Ms[e][ms + 2 * q + 1]);
        __half* dst = d_gt + ((size_t)(b * 4 + j - 1) * 64 + e) * 2048 + nn0 + ms;
        uint4* d4 = (uint4*)dst;
        d4[0] = *(uint4*)&h2[0];
        d4[1] = *(uint4*)&h2[4];
    }
}

// ---------------------------------------------------------------------------
// k_main: out[b, n0..n0+31, :] = x + g0 + sum_{l,m} adj[b,l,n,m] * g[b,l,m,:]
// 256 CTAs (64 m-tiles x 4 b), 2 CTAs/SM, cp.async 6-stage pipeline, fp16 MMA.
// 8 warps: warp grid 2m x 4n, warp tile 16x16.
// ---------------------------------------------------------------------------
__device__ __forceinline__ void issue_stage(int t, uint32_t sb, int tid,
                                            const float* __restrict__ adjb,
                                            const __half* __restrict__ gtb, int n0) {
    if (t < 128) {
        int slot = t % STAGES;
        int l = t >> 5, m0 = (t & 31) << 6;
        uint32_t aB = sb + slot * STAGE_BYTES;
        uint32_t bB = aB + A_ST;
        // A: 512 chunks (32 rows x 16), B: 512 chunks (64 rows x 8)
#pragma unroll
        for (int i = 0; i < 2; i++) {
            int ch = tid + i * 256;
            int row = ch >> 4, c16 = ch & 15;
            cpasync16(aB + row * A_ROW + c16 * 16,
                      adjb + ((size_t)l * N_ + n0 + row) * N_ + m0 + c16 * 4);
        }
#pragma unroll
        for (int i = 0; i < 2; i++) {
            int ch = tid + i * 256;
            int row = ch >> 3, c16 = ch & 7;
            cpasync16(bB + row * B_ROW + c16 * 16,
                      gtb + ((size_t)l * 64 + row) * 2048 + m0 + c16 * 8);
        }
    }
    asm volatile("cp.async.commit_group;");
}

__global__ void __launch_bounds__(256, 2)
k_main(const float* __restrict__ adj, const float* __restrict__ x,
       float* __restrict__ out) {
    extern __shared__ __align__(128) char smem[];
    uint32_t sb = smem_u32(smem);
    int tid = threadIdx.x, wid = tid >> 5, lane = tid & 31;
    int gid = lane >> 2, tig = lane & 3;
    int b = blockIdx.y;
    int n0 = blockIdx.x * 32;
    int warp_m = wid & 1, warp_n = wid >> 1;

    const float*  adjb = adj  + (size_t)b * L_ * N_ * N_;
    const __half* gtb  = d_gt + (size_t)b * 4 * 64 * 2048;

    // fragment addressing
    uint32_t ar_rel = (uint32_t)(warp_m * 16 + gid) * A_ROW + tig * 8;
    uint32_t bn_rel[2];
#pragma unroll
    for (int nt = 0; nt < 2; nt++)
        bn_rel[nt] = A_ST + (uint32_t)(warp_n * 16 + nt * 8 + gid) * B_ROW + tig * 4;

    float acc[2][4];
#pragma unroll
    for (int nt = 0; nt < 2; nt++)
#pragma unroll
        for (int q = 0; q < 4; q++) acc[nt][q] = 0.f;

    // prologue: stages 0..4
#pragma unroll
    for (int s = 0; s < STAGES - 1; s++) issue_stage(s, sb, tid, adjb, gtb, n0);

#pragma unroll 1
    for (int t = 0; t < 128; t++) {
        asm volatile("cp.async.wait_group %0;" :: "n"(STAGES - 2));
        __syncthreads();
        issue_stage(t + STAGES - 1, sb, tid, adjb, gtb, n0);

        uint32_t base = sb + (t % STAGES) * STAGE_BYTES;
        uint32_t ar = base + ar_rel;
#pragma unroll
        for (int ks = 0; ks < 4; ks++) {
            uint32_t afr[4];
#pragma unroll
            for (int kk = 0; kk < 2; kk++) {
                float x0, x1, y0, y1;
                lds_v2(x0, x1, ar + ks * 64 + kk * 32);
                lds_v2(y0, y1, ar + ks * 64 + kk * 32 + 8 * A_ROW);
                afr[kk * 2 + 0] = cvt_h2(x1, x0);
                afr[kk * 2 + 1] = cvt_h2(y1, y0);
            }
#pragma unroll
            for (int nt = 0; nt < 2; nt++) {
                uint32_t b0 = lds_b32(base + bn_rel[nt] + ks * 32);
                uint32_t b1 = lds_b32(base + bn_rel[nt] + ks * 32 + 16);
                mma16816(acc[nt], afr, b0, b1);
            }
        }
        __syncthreads();
    }

    // Epilogue: out = acc + x + g0
#pragma unroll
    for (int h = 0; h < 2; h++) {
        int node = n0 + warp_m * 16 + gid + 8 * h;
        size_t base = ((size_t)b * N_ + node) * 64;
#pragma unroll
        for (int nt = 0; nt < 2; nt++) {
            int col = warp_n * 16 + nt * 8 + 2 * tig;
            float2 xv = *(const float2*)(x + base + col);
            float2 gv = *(const float2*)(d_g0 + base + col);
            float2 o;
            o.x = acc[nt][h * 2 + 0] + xv.x + gv.x;
            o.y = acc[nt][h * 2 + 1] + xv.y + gv.y;
            *(float2*)(out + base + col) = o;
        }
    }
}

// ---------------------------------------------------------------------------
// Launch: x, feature, adj, fc_w, fc_b, ln_g, ln_b, W, a
// ---------------------------------------------------------------------------
extern "C" void kernel_launch(void* const* d_in, const int* in_sizes, int n_in,
                              void* d_out, int out_size) {
    const float* x    = (const float*)d_in[0];
    const float* feat = (const float*)d_in[1];
    const float* adj  = (const float*)d_in[2];
    const float* fcw  = (const float*)d_in[3];
    const float* fcb  = (const float*)d_in[4];
    const float* lng  = (const float*)d_in[5];
    const float* lnb  = (const float*)d_in[6];
    const float* W    = (const float*)d_in[7];
    const float* a    = (const float*)d_in[8];
    float* out = (float*)d_out;

    cudaFuncSetAttribute(k_main, cudaFuncAttributeMaxDynamicSharedMemorySize, SMEM_MAIN);

    k_M<<<80, 256>>>(W, a);
    k_h<<<1024, 256>>>(x, feat, fcw, fcb, lng, lnb);
    k_g<<<dim3(128, 5), 256>>>();
    k_main<<<dim3(64, 4), 256, SMEM_MAIN>>>(adj, x, out);
}

// round 6
// speedup vs baseline: 1.6720x; 1.4121x over previous
#include <cuda_runtime.h>
#include <cuda_fp16.h>
#include <cstdint>

// Problem constants: B=4, L=4, N=2048, H=64, V=4, label_plus1=5
#define B_    4
#define L_    4
#define N_    2048
#define H_    64

// k_main pipeline (CTA tile 64m x 64e, k-tile 64, 1 CTA/SM, 128 CTAs)
#define STAGES      8
#define A_ROW       288                  // 256B content + 32B pad (conflict-free lds_v2)
#define B_ROW       144                  // 128B content + 16B pad
#define A_ST        (64 * A_ROW)         // 18432
#define B_ST        (64 * B_ROW)         // 9216
#define STAGE_BYTES (A_ST + B_ST)        // 27648
#define SMEM_MAIN   (STAGES * STAGE_BYTES)   // 221184

// Scratch (device globals; no allocation allowed)
__device__ __align__(128) float  d_h [B_ * N_ * H_];
__device__ __align__(128) float  d_g0[B_ * N_ * H_];
__device__ __align__(128) __half d_gt[B_ * 4 * H_ * N_];   // [b,l,e,m] fp16

// ---------------------------------------------------------------------------
// Helpers
// ---------------------------------------------------------------------------
__device__ __forceinline__ uint32_t smem_u32(const void* p) {
    uint32_t a;
    asm("{ .reg .u64 t; cvta.to.shared.u64 t, %1; cvt.u32.u64 %0, t; }" : "=r"(a) : "l"(p));
    return a;
}
__device__ __forceinline__ void cpasync16(uint32_t saddr, const void* gaddr) {
    asm volatile("cp.async.cg.shared.global [%0], [%1], 16;" :: "r"(saddr), "l"(gaddr));
}
__device__ __forceinline__ void lds_v2(float& x, float& y, uint32_t a) {
    asm volatile("ld.shared.v2.f32 {%0, %1}, [%2];" : "=f"(x), "=f"(y) : "r"(a));
}
__device__ __forceinline__ uint32_t lds_b32(uint32_t a) {
    uint32_t v;
    asm volatile("ld.shared.b32 %0, [%1];" : "=r"(v) : "r"(a));
    return v;
}
__device__ __forceinline__ uint32_t cvt_h2(float hi, float lo) {   // pack {lo, hi}
    uint32_t r;
    asm("cvt.rn.f16x2.f32 %0, %1, %2;" : "=r"(r) : "f"(hi), "f"(lo));
    return r;
}
__device__ __forceinline__ void mma16816(float* c, const uint32_t* a, uint32_t b0, uint32_t b1) {
    asm volatile(
        "mma.sync.aligned.m16n8k16.row.col.f32.f16.f16.f32 "
        "{%0,%1,%2,%3}, {%4,%5,%6,%7}, {%8,%9}, {%0,%1,%2,%3};"
        : "+f"(c[0]), "+f"(c[1]), "+f"(c[2]), "+f"(c[3])
        : "r"(a[0]), "r"(a[1]), "r"(a[2]), "r"(a[3]), "r"(b0), "r"(b1));
}
__device__ __forceinline__ float fast_tanh(float x) {
    float t = exp2f(x * 2.8853900817779268f);
    return 1.0f - __fdividef(2.0f, t + 1.0f);
}

// ---------------------------------------------------------------------------
// k_h: h = fast_tanh(LayerNorm(concat(x,feat) @ fc_w^T + fc_b))
// ---------------------------------------------------------------------------
__global__ void k_h(const float* __restrict__ x, const float* __restrict__ feat,
                    const float* __restrict__ fcw, const float* __restrict__ fcb,
                    const float* __restrict__ lng, const float* __restrict__ lnb) {
    __shared__ float sw[64 * 66];
    __shared__ float sp[3][64];
    __shared__ float srow[8][68];
    int tid = threadIdx.x;
    for (int i = tid; i < 64 * 66; i += 256) sw[i] = fcw[i];
    if (tid < 64) { sp[0][tid] = fcb[tid]; sp[1][tid] = lng[tid]; sp[2][tid] = lnb[tid]; }
    int warp = tid >> 5, lane = tid & 31;
    int row = blockIdx.x * 8 + warp;
    srow[warp][lane]      = x[row * 64 + lane];
    srow[warp][lane + 32] = x[row * 64 + lane + 32];
    if (lane < 2) srow[warp][64 + lane] = feat[row * 2 + lane];
    __syncthreads();

    float h0 = sp[0][lane], h1 = sp[0][lane + 32];
#pragma unroll
    for (int k = 0; k < 66; k++) {
        float xk = srow[warp][k];
        h0 += sw[lane * 66 + k] * xk;
        h1 += sw[(lane + 32) * 66 + k] * xk;
    }
    float s = h0 + h1, sq = h0 * h0 + h1 * h1;
#pragma unroll
    for (int o = 16; o > 0; o >>= 1) {
        s  += __shfl_xor_sync(0xffffffff, s,  o);
        sq += __shfl_xor_sync(0xffffffff, sq, o);
    }
    float mu  = s * (1.f / 64.f);
    float var = sq * (1.f / 64.f) - mu * mu;
    float inv = rsqrtf(var + 1e-5f);
    h0 = fast_tanh((h0 - mu) * inv * sp[1][lane]      + sp[2][lane]);
    h1 = fast_tanh((h1 - mu) * inv * sp[1][lane + 32] + sp[2][lane + 32]);
    d_h[row * 64 + lane]      = h0;
    d_h[row * 64 + lane + 32] = h1;
}

// ---------------------------------------------------------------------------
// k_g: M_j = (a_j @ W)/5 computed in-block, then g_j = h @ M_j.
// Grid (128 row-tiles, 5 j). j=0 -> d_g0 fp32; j>=1 -> d_gt [b,j-1,e,m] fp16.
// ---------------------------------------------------------------------------
__global__ void k_g(const float* __restrict__ W, const float* __restrict__ a) {
    __shared__ float Ms[64][65];
    __shared__ float hs[64][65];
    int tid = threadIdx.x;
    int j = blockIdx.y;
    int row0 = blockIdx.x * 64;
    int b = row0 >> 11, nn0 = row0 & 2047;
    float a0 = a[j * 4 + 0], a1 = a[j * 4 + 1], a2 = a[j * 4 + 2], a3 = a[j * 4 + 3];
    for (int i = tid; i < 4096; i += 256) {
        hs[i >> 6][i & 63] = d_h[(size_t)row0 * 64 + i];
        int d = i >> 6, e = i & 63;
        const float* wp = W + (size_t)(d * 4) * 64 + e;
        Ms[d][e] = (a0 * wp[0] + a1 * wp[64] + a2 * wp[128] + a3 * wp[192]) * 0.2f;
    }
    __syncthreads();
    int r = tid >> 2, c0 = (tid & 3) * 16;
    float acc[16];
#pragma unroll
    for (int c = 0; c < 16; c++) acc[c] = 0.f;
#pragma unroll 8
    for (int d = 0; d < 64; d++) {
        float hv = hs[r][d];
#pragma unroll
        for (int c = 0; c < 16; c++) acc[c] += hv * Ms[d][c0 + c];
    }
    if (j == 0) {
        float* dst = d_g0 + ((size_t)row0 + r) * 64 + c0;
#pragma unroll
        for (int c = 0; c < 16; c++) dst[c] = acc[c];
    } else {
        __syncthreads();
#pragma unroll
        for (int c = 0; c < 16; c++) Ms[c0 + c][r] = acc[c];   // transpose
        __syncthreads();
        int e = tid >> 2, ms = (tid & 3) * 16;
        __half2 h2[8];
#pragma unroll
        for (int q = 0; q < 8; q++)
            h2[q] = __floats2half2_rn(Ms[e][ms + 2 * q], Ms[e][ms + 2 * q + 1]);
        __half* dst = d_gt + ((size_t)(b * 4 + j - 1) * 64 + e) * 2048 + nn0 + ms;
        uint4* d4 = (uint4*)dst;
        d4[0] = *(uint4*)&h2[0];
        d4[1] = *(uint4*)&h2[4];
    }
}

// ---------------------------------------------------------------------------
// k_main: out[b, n0..n0+63, :] = x + g0 + sum_{l,m} adj[b,l,n,m] * g[b,l,m,:]
// 128 CTAs (32 m-tiles x 4 b), 1 CTA/SM, cp.async 8-stage pipeline, fp16 MMA.
// 8 warps: warp grid 4m x 2n, warp tile 16x32.
// ---------------------------------------------------------------------------
__device__ __forceinline__ void issue_stage(int t, uint32_t sb, int tid,
                                            const float* __restrict__ adjb,
                                            const __half* __restrict__ gtb, int n0) {
    if (t < 128) {
        int slot = t & (STAGES - 1);
        int l = t >> 5, m0 = (t & 31) << 6;
        uint32_t aB = sb + slot * STAGE_BYTES;
        uint32_t bB = aB + A_ST;
        // A: 1024 chunks (64 rows x 16); B: 512 chunks (64 rows x 8)
#pragma unroll
        for (int i = 0; i < 4; i++) {
            int ch = tid + i * 256;
            int row = ch >> 4, c16 = ch & 15;
            cpasync16(aB + row * A_ROW + c16 * 16,
                      adjb + ((size_t)l * N_ + n0 + row) * N_ + m0 + c16 * 4);
        }
#pragma unroll
        for (int i = 0; i < 2; i++) {
            int ch = tid + i * 256;
            int row = ch >> 3, c16 = ch & 7;
            cpasync16(bB + row * B_ROW + c16 * 16,
                      gtb + ((size_t)l * 64 + row) * 2048 + m0 + c16 * 8);
        }
    }
    asm volatile("cp.async.commit_group;");
}

__global__ void __launch_bounds__(256, 1)
k_main(const float* __restrict__ adj, const float* __restrict__ x,
       float* __restrict__ out) {
    extern __shared__ __align__(128) char smem[];
    uint32_t sb = smem_u32(smem);
    int tid = threadIdx.x, wid = tid >> 5, lane = tid & 31;
    int gid = lane >> 2, tig = lane & 3;
    int b = blockIdx.y;
    int n0 = blockIdx.x * 64;
    int warp_m = wid & 3, warp_n = wid >> 2;

    const float*  adjb = adj  + (size_t)b * L_ * N_ * N_;
    const __half* gtb  = d_gt + (size_t)b * 4 * 64 * 2048;

    // fragment addressing
    uint32_t ar_rel = (uint32_t)(warp_m * 16 + gid) * A_ROW + tig * 8;
    uint32_t bn_rel[4];
#pragma unroll
    for (int nt = 0; nt < 4; nt++)
        bn_rel[nt] = A_ST + (uint32_t)(warp_n * 32 + nt * 8 + gid) * B_ROW + tig * 4;

    float acc[4][4];
#pragma unroll
    for (int nt = 0; nt < 4; nt++)
#pragma unroll
        for (int q = 0; q < 4; q++) acc[nt][q] = 0.f;

    // prologue: stages 0..6
#pragma unroll
    for (int s = 0; s < STAGES - 1; s++) issue_stage(s, sb, tid, adjb, gtb, n0);

#pragma unroll 1
    for (int t = 0; t < 128; t++) {
        asm volatile("cp.async.wait_group %0;" :: "n"(STAGES - 2));
        __syncthreads();
        issue_stage(t + STAGES - 1, sb, tid, adjb, gtb, n0);

        uint32_t base = sb + (t & (STAGES - 1)) * STAGE_BYTES;
        uint32_t ar = base + ar_rel;
#pragma unroll
        for (int ks = 0; ks < 4; ks++) {
            uint32_t afr[4];
#pragma unroll
            for (int kk = 0; kk < 2; kk++) {
                float x0, x1, y0, y1;
                lds_v2(x0, x1, ar + ks * 64 + kk * 32);
                lds_v2(y0, y1, ar + ks * 64 + kk * 32 + 8 * A_ROW);
                afr[kk * 2 + 0] = cvt_h2(x1, x0);
                afr[kk * 2 + 1] = cvt_h2(y1, y0);
            }
#pragma unroll
            for (int nt = 0; nt < 4; nt++) {
                uint32_t b0 = lds_b32(base + bn_rel[nt] + ks * 32);
                uint32_t b1 = lds_b32(base + bn_rel[nt] + ks * 32 + 16);
                mma16816(acc[nt], afr, b0, b1);
            }
        }
        __syncthreads();
    }

    // Epilogue: out = acc + x + g0
#pragma unroll
    for (int h = 0; h < 2; h++) {
        int node = n0 + warp_m * 16 + gid + 8 * h;
        size_t base = ((size_t)b * N_ + node) * 64;
#pragma unroll
        for (int nt = 0; nt < 4; nt++) {
            int col = warp_n * 32 + nt * 8 + 2 * tig;
            float2 xv = *(const float2*)(x + base + col);
            float2 gv = *(const float2*)(d_g0 + base + col);
            float2 o;
            o.x = acc[nt][h * 2 + 0] + xv.x + gv.x;
            o.y = acc[nt][h * 2 + 1] + xv.y + gv.y;
            *(float2*)(out + base + col) = o;
        }
    }
}

// ---------------------------------------------------------------------------
// Launch: x, feature, adj, fc_w, fc_b, ln_g, ln_b, W, a
// ---------------------------------------------------------------------------
extern "C" void kernel_launch(void* const* d_in, const int* in_sizes, int n_in,
                              void* d_out, int out_size) {
    const float* x    = (const float*)d_in[0];
    const float* feat = (const float*)d_in[1];
    const float* adj  = (const float*)d_in[2];
    const float* fcw  = (const float*)d_in[3];
    const float* fcb  = (const float*)d_in[4];
    const float* lng  = (const float*)d_in[5];
    const float* lnb  = (const float*)d_in[6];
    const float* W    = (const float*)d_in[7];
    const float* a    = (const float*)d_in[8];
    float* out = (float*)d_out;

    cudaFuncSetAttribute(k_main, cudaFuncAttributeMaxDynamicSharedMemorySize, SMEM_MAIN);

    k_h<<<1024, 256>>>(x, feat, fcw, fcb, lng, lnb);
    k_g<<<dim3(128, 5), 256>>>(W, a);
    k_main<<<dim3(32, 4), 256, SMEM_MAIN>>>(adj, x, out);
}

// round 7
// speedup vs baseline: 1.7620x; 1.0538x over previous
#include <cuda_runtime.h>
#include <cuda_fp16.h>
#include <cstdint>

// Problem constants: B=4, L=4, N=2048, H=64, V=4, label_plus1=5
#define B_    4
#define L_    4
#define N_    2048
#define H_    64

// k_main pipeline (CTA tile 64m x 64e, k-tile 64, split-K by 2, 2 CTAs/SM)
#define STAGES      4
#define A_ROW       288                  // 256B content + 32B pad (conflict-free lds_v2)
#define B_ROW       144                  // 128B content + 16B pad
#define A_ST        (64 * A_ROW)         // 18432
#define B_ST        (64 * B_ROW)         // 9216
#define STAGE_BYTES (A_ST + B_ST)        // 27648
#define SMEM_MAIN   (STAGES * STAGE_BYTES)   // 110592

// Scratch (device globals; no allocation allowed)
__device__ __align__(128) float  d_h [B_ * N_ * H_];
__device__ __align__(128) float  d_g0[B_ * N_ * H_];
__device__ __align__(128) __half d_gt[B_ * 4 * H_ * N_];   // [b,l,e,m] fp16

// ---------------------------------------------------------------------------
// Helpers
// ---------------------------------------------------------------------------
__device__ __forceinline__ uint32_t smem_u32(const void* p) {
    uint32_t a;
    asm("{ .reg .u64 t; cvta.to.shared.u64 t, %1; cvt.u32.u64 %0, t; }" : "=r"(a) : "l"(p));
    return a;
}
__device__ __forceinline__ void cpasync16(uint32_t saddr, const void* gaddr) {
    asm volatile("cp.async.cg.shared.global [%0], [%1], 16;" :: "r"(saddr), "l"(gaddr));
}
__device__ __forceinline__ void lds_v2(float& x, float& y, uint32_t a) {
    asm volatile("ld.shared.v2.f32 {%0, %1}, [%2];" : "=f"(x), "=f"(y) : "r"(a));
}
__device__ __forceinline__ uint32_t lds_b32(uint32_t a) {
    uint32_t v;
    asm volatile("ld.shared.b32 %0, [%1];" : "=r"(v) : "r"(a));
    return v;
}
__device__ __forceinline__ uint32_t cvt_h2(float hi, float lo) {   // pack {lo, hi}
    uint32_t r;
    asm("cvt.rn.f16x2.f32 %0, %1, %2;" : "=r"(r) : "f"(hi), "f"(lo));
    return r;
}
__device__ __forceinline__ void mma16816(float* c, const uint32_t* a, uint32_t b0, uint32_t b1) {
    asm volatile(
        "mma.sync.aligned.m16n8k16.row.col.f32.f16.f16.f32 "
        "{%0,%1,%2,%3}, {%4,%5,%6,%7}, {%8,%9}, {%0,%1,%2,%3};"
        : "+f"(c[0]), "+f"(c[1]), "+f"(c[2]), "+f"(c[3])
        : "r"(a[0]), "r"(a[1]), "r"(a[2]), "r"(a[3]), "r"(b0), "r"(b1));
}
__device__ __forceinline__ void red_add(float* p, float v) {
    asm volatile("red.global.add.f32 [%0], %1;" :: "l"(p), "f"(v) : "memory");
}
__device__ __forceinline__ float fast_tanh(float x) {
    float t = exp2f(x * 2.8853900817779268f);
    return 1.0f - __fdividef(2.0f, t + 1.0f);
}

// ---------------------------------------------------------------------------
// k_h: h = fast_tanh(LayerNorm(concat(x,feat) @ fc_w^T + fc_b))
// ---------------------------------------------------------------------------
__global__ void k_h(const float* __restrict__ x, const float* __restrict__ feat,
                    const float* __restrict__ fcw, const float* __restrict__ fcb,
                    const float* __restrict__ lng, const float* __restrict__ lnb) {
    __shared__ float sw[64 * 66];
    __shared__ float sp[3][64];
    __shared__ float srow[8][68];
    int tid = threadIdx.x;
    for (int i = tid; i < 64 * 66; i += 256) sw[i] = fcw[i];
    if (tid < 64) { sp[0][tid] = fcb[tid]; sp[1][tid] = lng[tid]; sp[2][tid] = lnb[tid]; }
    int warp = tid >> 5, lane = tid & 31;
    int row = blockIdx.x * 8 + warp;
    srow[warp][lane]      = x[row * 64 + lane];
    srow[warp][lane + 32] = x[row * 64 + lane + 32];
    if (lane < 2) srow[warp][64 + lane] = feat[row * 2 + lane];
    __syncthreads();

    float h0 = sp[0][lane], h1 = sp[0][lane + 32];
#pragma unroll
    for (int k = 0; k < 66; k++) {
        float xk = srow[warp][k];
        h0 += sw[lane * 66 + k] * xk;
        h1 += sw[(lane + 32) * 66 + k] * xk;
    }
    float s = h0 + h1, sq = h0 * h0 + h1 * h1;
#pragma unroll
    for (int o = 16; o > 0; o >>= 1) {
        s  += __shfl_xor_sync(0xffffffff, s,  o);
        sq += __shfl_xor_sync(0xffffffff, sq, o);
    }
    float mu  = s * (1.f / 64.f);
    float var = sq * (1.f / 64.f) - mu * mu;
    float inv = rsqrtf(var + 1e-5f);
    h0 = fast_tanh((h0 - mu) * inv * sp[1][lane]      + sp[2][lane]);
    h1 = fast_tanh((h1 - mu) * inv * sp[1][lane + 32] + sp[2][lane + 32]);
    d_h[row * 64 + lane]      = h0;
    d_h[row * 64 + lane + 32] = h1;
}

// ---------------------------------------------------------------------------
// k_g: M_j = (a_j @ W)/5 in-block, then g_j = h @ M_j.
// Grid (128 row-tiles, 5 j). j=0 -> d_g0 fp32; j>=1 -> d_gt [b,j-1,e,m] fp16.
// ---------------------------------------------------------------------------
__global__ void k_g(const float* __restrict__ W, const float* __restrict__ a) {
    __shared__ float Ms[64][65];
    __shared__ float hs[64][65];
    int tid = threadIdx.x;
    int j = blockIdx.y;
    int row0 = blockIdx.x * 64;
    int b = row0 >> 11, nn0 = row0 & 2047;
    float a0 = a[j * 4 + 0], a1 = a[j * 4 + 1], a2 = a[j * 4 + 2], a3 = a[j * 4 + 3];
    for (int i = tid; i < 4096; i += 256) {
        hs[i >> 6][i & 63] = d_h[(size_t)row0 * 64 + i];
        int d = i >> 6, e = i & 63;
        const float* wp = W + (size_t)(d * 4) * 64 + e;
        Ms[d][e] = (a0 * wp[0] + a1 * wp[64] + a2 * wp[128] + a3 * wp[192]) * 0.2f;
    }
    __syncthreads();
    int r = tid >> 2, c0 = (tid & 3) * 16;
    float acc[16];
#pragma unroll
    for (int c = 0; c < 16; c++) acc[c] = 0.f;
#pragma unroll 8
    for (int d = 0; d < 64; d++) {
        float hv = hs[r][d];
#pragma unroll
        for (int c = 0; c < 16; c++) acc[c] += hv * Ms[d][c0 + c];
    }
    if (j == 0) {
        float* dst = d_g0 + ((size_t)row0 + r) * 64 + c0;
#pragma unroll
        for (int c = 0; c < 16; c++) dst[c] = acc[c];
    } else {
        __syncthreads();
#pragma unroll
        for (int c = 0; c < 16; c++) Ms[c0 + c][r] = acc[c];   // transpose
        __syncthreads();
        int e = tid >> 2, ms = (tid & 3) * 16;
        __half2 h2[8];
#pragma unroll
        for (int q = 0; q < 8; q++)
            h2[q] = __floats2half2_rn(Ms[e][ms + 2 * q], Ms[e][ms + 2 * q + 1]);
        __half* dst = d_gt + ((size_t)(b * 4 + j - 1) * 64 + e) * 2048 + nn0 + ms;
        uint4* d4 = (uint4*)dst;
        d4[0] = *(uint4*)&h2[0];
        d4[1] = *(uint4*)&h2[4];
    }
}

// ---------------------------------------------------------------------------
// k_init: out = x + g0  (k_main then red.adds its partials on top)
// ---------------------------------------------------------------------------
__global__ void k_init(const float* __restrict__ x, float* __restrict__ out) {
    int i = blockIdx.x * 256 + threadIdx.x;        // float4 index, 131072 total
    float4 xv = ((const float4*)x)[i];
    float4 gv = ((const float4*)d_g0)[i];
    float4 o;
    o.x = xv.x + gv.x; o.y = xv.y + gv.y; o.z = xv.z + gv.z; o.w = xv.w + gv.w;
    ((float4*)out)[i] = o;
}

// ---------------------------------------------------------------------------
// k_main: partial[b, n0..n0+63, :] = sum_{l in khalf, m} adj[b,l,n,m]*g[b,l,m,:]
// Split-K: 256 CTAs (32 m-tiles x 4 b x 2 khalf), 2 CTAs/SM.
// 4-stage cp.async pipeline, fp16 MMA, warp grid 4m x 2n (warp tile 16x32).
// Epilogue: red.global.add.f32 into out.
// ---------------------------------------------------------------------------
__device__ __forceinline__ void issue_stage(int t, uint32_t sb, int tid,
                                            const float* __restrict__ adjb,
                                            const __half* __restrict__ gtb, int n0) {
    if (t < 64) {
        int slot = t & (STAGES - 1);
        int l = t >> 5, m0 = (t & 31) << 6;
        uint32_t aB = sb + slot * STAGE_BYTES;
        uint32_t bB = aB + A_ST;
#pragma unroll
        for (int i = 0; i < 4; i++) {
            int ch = tid + i * 256;
            int row = ch >> 4, c16 = ch & 15;
            cpasync16(aB + row * A_ROW + c16 * 16,
                      adjb + ((size_t)l * N_ + n0 + row) * N_ + m0 + c16 * 4);
        }
#pragma unroll
        for (int i = 0; i < 2; i++) {
            int ch = tid + i * 256;
            int row = ch >> 3, c16 = ch & 7;
            cpasync16(bB + row * B_ROW + c16 * 16,
                      gtb + ((size_t)l * 64 + row) * 2048 + m0 + c16 * 8);
        }
    }
    asm volatile("cp.async.commit_group;");
}

__global__ void __launch_bounds__(256, 2)
k_main(const float* __restrict__ adj, float* __restrict__ out) {
    extern __shared__ __align__(128) char smem[];
    uint32_t sb = smem_u32(smem);
    int tid = threadIdx.x, wid = tid >> 5, lane = tid & 31;
    int gid = lane >> 2, tig = lane & 3;
    int b = blockIdx.y;
    int n0 = blockIdx.x * 64;
    int kh = blockIdx.z;                 // K half: l in {2kh, 2kh+1}
    int warp_m = wid & 3, warp_n = wid >> 2;

    const float*  adjb = adj  + ((size_t)b * L_ + 2 * kh) * N_ * N_;
    const __half* gtb  = d_gt + (size_t)(b * 4 + 2 * kh) * 64 * 2048;

    uint32_t ar_rel = (uint32_t)(warp_m * 16 + gid) * A_ROW + tig * 8;
    uint32_t bn_rel[4];
#pragma unroll
    for (int nt = 0; nt < 4; nt++)
        bn_rel[nt] = A_ST + (uint32_t)(warp_n * 32 + nt * 8 + gid) * B_ROW + tig * 4;

    float acc[4][4];
#pragma unroll
    for (int nt = 0; nt < 4; nt++)
#pragma unroll
        for (int q = 0; q < 4; q++) acc[nt][q] = 0.f;

    // prologue: stages 0..2
#pragma unroll
    for (int s = 0; s < STAGES - 1; s++) issue_stage(s, sb, tid, adjb, gtb, n0);

#pragma unroll 1
    for (int t = 0; t < 64; t++) {
        asm volatile("cp.async.wait_group %0;" :: "n"(STAGES - 2));
        __syncthreads();
        issue_stage(t + STAGES - 1, sb, tid, adjb, gtb, n0);

        uint32_t base = sb + (t & (STAGES - 1)) * STAGE_BYTES;
        uint32_t ar = base + ar_rel;
#pragma unroll
        for (int ks = 0; ks < 4; ks++) {
            uint32_t afr[4];
#pragma unroll
            for (int kk = 0; kk < 2; kk++) {
                float x0, x1, y0, y1;
                lds_v2(x0, x1, ar + ks * 64 + kk * 32);
                lds_v2(y0, y1, ar + ks * 64 + kk * 32 + 8 * A_ROW);
                afr[kk * 2 + 0] = cvt_h2(x1, x0);
                afr[kk * 2 + 1] = cvt_h2(y1, y0);
            }
#pragma unroll
            for (int nt = 0; nt < 4; nt++) {
                uint32_t b0 = lds_b32(base + bn_rel[nt] + ks * 32);
                uint32_t b1 = lds_b32(base + bn_rel[nt] + ks * 32 + 16);
                mma16816(acc[nt], afr, b0, b1);
            }
        }
        __syncthreads();
    }

    // Epilogue: atomically accumulate partials into out (= x + g0 from k_init)
#pragma unroll
    for (int h = 0; h < 2; h++) {
        int node = n0 + warp_m * 16 + gid + 8 * h;
        float* basep = out + ((size_t)b * N_ + node) * 64;
#pragma unroll
        for (int nt = 0; nt < 4; nt++) {
            int col = warp_n * 32 + nt * 8 + 2 * tig;
            red_add(basep + col,     acc[nt][h * 2 + 0]);
            red_add(basep + col + 1, acc[nt][h * 2 + 1]);
        }
    }
}

// ---------------------------------------------------------------------------
// Launch: x, feature, adj, fc_w, fc_b, ln_g, ln_b, W, a
// ---------------------------------------------------------------------------
extern "C" void kernel_launch(void* const* d_in, const int* in_sizes, int n_in,
                              void* d_out, int out_size) {
    const float* x    = (const float*)d_in[0];
    const float* feat = (const float*)d_in[1];
    const float* adj  = (const float*)d_in[2];
    const float* fcw  = (const float*)d_in[3];
    const float* fcb  = (const float*)d_in[4];
    const float* lng  = (const float*)d_in[5];
    const float* lnb  = (const float*)d_in[6];
    const float* W    = (const float*)d_in[7];
    const float* a    = (const float*)d_in[8];
    float* out = (float*)d_out;

    cudaFuncSetAttribute(k_main, cudaFuncAttributeMaxDynamicSharedMemorySize, SMEM_MAIN);

    k_h<<<1024, 256>>>(x, feat, fcw, fcb, lng, lnb);
    k_g<<<dim3(128, 5), 256>>>(W, a);
    k_init<<<512, 256>>>(x, out);
    k_main<<<dim3(32, 4, 2), 256, SMEM_MAIN>>>(adj, out);
}